// round 14
// baseline (speedup 1.0000x reference)
#include <cuda_runtime.h>

#define BB 4
#define SS 1024
#define DD 1024
#define HH 16
#define HS 64
#define TQ 16
#define TK 128
#define SCP 1028
#define QSTR 17

typedef unsigned long long ull;

// Scratch (no allocations allowed -> __device__ globals)
__device__ float g_Q[BB * HH * SS * HS];     // [b,h,s,e] 16 MB
__device__ float g_K[BB * HH * SS * HS];     // [b,h,s,e] 16 MB
__device__ float g_V[BB * SS * HS];          // [b,s,e]    1 MB
__device__ float g_AWp[BB * 4 * SS * SS];    // per-headgroup partial attn  67 MB
__device__ float g_O1p[BB * 4 * SS * HS];    // per-headgroup partial ctx    4 MB

// ---- packed fp32x2 helpers (bit-exact fp32 FMA, 2x throughput) ----
__device__ __forceinline__ ull pk2(float x, float y) {
    ull r; asm("mov.b64 %0,{%1,%2};" : "=l"(r) : "f"(x), "f"(y)); return r;
}
__device__ __forceinline__ float2 upk2(ull v) {
    float2 r; asm("mov.b64 {%0,%1},%2;" : "=f"(r.x), "=f"(r.y) : "l"(v)); return r;
}
__device__ __forceinline__ ull ffma2(ull a, ull b, ull c) {
    ull d; asm("fma.rn.f32x2 %0,%1,%2,%3;" : "=l"(d) : "l"(a), "l"(b), "l"(c)); return d;
}

// ---------------------------------------------------------------------------
// Projection GEMM with FFMA2: out(m,n) = A[m,:] @ W[h][:,n] + bias
// Tile 64x64, 256 threads, 4x4 micro-tile (as 4x2 packed pairs), K-tile 16.
// ---------------------------------------------------------------------------
__global__ void proj_gemm(const float* __restrict__ A, const float* __restrict__ W,
                          const float* __restrict__ bias, float* __restrict__ out,
                          int strideB, int strideH) {
    __shared__ float As[16][68];   // 68: keeps float4 reads 16B-aligned
    __shared__ float Bs[16][64];
    const int tid = threadIdx.x;
    const int tx = tid & 15, ty = tid >> 4;
    const int n0 = blockIdx.x * 64;
    const int m0 = blockIdx.y * 64;
    const float* Wh = W + (size_t)blockIdx.x * (DD * HS);

    ull acc[4][2];
#pragma unroll
    for (int i = 0; i < 4; ++i) { acc[i][0] = 0ull; acc[i][1] = 0ull; }

    for (int k0 = 0; k0 < DD; k0 += 16) {
        {
            int ml = tid >> 2, kk4 = (tid & 3) * 4;
            float4 a4 = *(const float4*)(A + (size_t)(m0 + ml) * DD + k0 + kk4);
            As[kk4 + 0][ml] = a4.x;
            As[kk4 + 1][ml] = a4.y;
            As[kk4 + 2][ml] = a4.z;
            As[kk4 + 3][ml] = a4.w;
        }
        {
            int kk = tid >> 4, nl4 = (tid & 15) * 4;
            *(float4*)&Bs[kk][nl4] = *(const float4*)(Wh + (size_t)(k0 + kk) * HS + nl4);
        }
        __syncthreads();

#pragma unroll
        for (int kk = 0; kk < 16; ++kk) {
            float4 a4 = *(const float4*)&As[kk][ty * 4];
            ulonglong2 bb = *(const ulonglong2*)&Bs[kk][tx * 4];
            ull aa;
            aa = pk2(a4.x, a4.x); acc[0][0] = ffma2(aa, bb.x, acc[0][0]); acc[0][1] = ffma2(aa, bb.y, acc[0][1]);
            aa = pk2(a4.y, a4.y); acc[1][0] = ffma2(aa, bb.x, acc[1][0]); acc[1][1] = ffma2(aa, bb.y, acc[1][1]);
            aa = pk2(a4.z, a4.z); acc[2][0] = ffma2(aa, bb.x, acc[2][0]); acc[2][1] = ffma2(aa, bb.y, acc[2][1]);
            aa = pk2(a4.w, a4.w); acc[3][0] = ffma2(aa, bb.x, acc[3][0]); acc[3][1] = ffma2(aa, bb.y, acc[3][1]);
        }
        __syncthreads();
    }

#pragma unroll
    for (int i = 0; i < 4; ++i) {
        int m = m0 + ty * 4 + i;
        int b = m >> 10, srow = m & 1023;
        float* orow = out + (size_t)b * strideB + (size_t)blockIdx.x * strideH + (size_t)srow * HS;
        float2 lo = upk2(acc[i][0]), hi = upk2(acc[i][1]);
        int nl = tx * 4;
        orow[nl + 0] = lo.x + bias[n0 + nl + 0];
        orow[nl + 1] = lo.y + bias[n0 + nl + 1];
        orow[nl + 2] = hi.x + bias[n0 + nl + 2];
        orow[nl + 3] = hi.y + bias[n0 + nl + 3];
    }
}

// ---------------------------------------------------------------------------
// Attention v3: one CTA per (b, qtile=16 rows, headgroup of 4 heads).
// 256 threads, ~109KB smem -> 2 CTAs/SM. FFMA2 inner loops. Partial head-mean
// attn rows accumulate into a CTA-exclusive global buffer (no atomics).
// ---------------------------------------------------------------------------
// smem float offsets:
//   SC : 16*1028            @ 0       (scores row buffer)
//   KV : 8704               @ 16448   (KsT: 64 x 128 | Vs: 128 x 68, union)
//   QP : 64*17 ull (=2176f) @ 25152   (Q splat-pairs, [e][qi])
//   INV: 16                 @ 27328
#define KV_OFF   16448
#define QP_OFF   25152
#define INV_OFF  27328
#define ATTN_SMEM ((INV_OFF + 16) * 4)   // 109376 bytes

__global__ __launch_bounds__(256, 2) void attn3_kernel() {
    extern __shared__ float sm[];
    float* SCb = sm;
    float* KVb = sm + KV_OFF;
    ull*   QPb = (ull*)(sm + QP_OFF);
    float* INVb = sm + INV_OFF;

    const int qt = 63 - (int)blockIdx.x;   // reversed for load balance
    const int hg = blockIdx.y;
    const int b  = blockIdx.z;
    const int tid = threadIdx.x;
    const int lane = tid & 31;
    const int w = tid >> 5;

    const int s0 = qt * TQ;
    const int ntiles = (s0 + TQ + TK - 1) >> 7;
    const int tilemax = ntiles << 7;

    // scores mapping: warp w owns t-window [16w,16w+16) of each tile, all 16 q.
    // thread: q-pair = lane>>2, t-quad = lane&3.
    const int qp = lane >> 2;                  // 0..7 -> rows 2qp, 2qp+1
    const int kq = 16 * w + 4 * (lane & 3);    // t offset within tile

    // PV mapping: warp tile 8q x 16e, thread 1q x 4e
    const int pv_qi = (w >> 2) * 8 + (lane >> 2);
    const int pv_e4 = (w & 3) * 4 + (lane & 3);

    float* gAW = g_AWp + (((size_t)(b * 4 + hg)) * SS + s0) * SS;
    const float* Vb = g_V + (size_t)b * SS * HS;

    ull ctx01 = 0ull, ctx23 = 0ull;

    for (int hh = 0; hh < 4; ++hh) {
        const int h = hg * 4 + hh;
        const size_t bh = (size_t)(b * HH + h);
        __syncthreads();  // prev head's PV/INV readers done

        // --- load Q tile as splat pairs: QP[e][qi] = (q,q) ---
        {
            int qi = tid & 15, eB = tid >> 4;
            float4 v = *(const float4*)(g_Q + (bh * SS + s0 + qi) * HS + eB * 4);
            QPb[(eB * 4 + 0) * QSTR + qi] = pk2(v.x, v.x);
            QPb[(eB * 4 + 1) * QSTR + qi] = pk2(v.y, v.y);
            QPb[(eB * 4 + 2) * QSTR + qi] = pk2(v.z, v.z);
            QPb[(eB * 4 + 3) * QSTR + qi] = pk2(v.w, v.w);
        }

        // --- scores ---
        for (int tile = 0; tile < ntiles; ++tile) {
            const int t0 = tile << 7;
            __syncthreads();
            {   // K tile transposed: KsT[e][t]
                int tl = tid & 127, eh = tid >> 7;
                const float4* src = (const float4*)(g_K + (bh * SS + t0 + tl) * HS) + eh * 8;
#pragma unroll
                for (int i = 0; i < 8; ++i) {
                    float4 v = src[i];
                    int e = eh * 32 + i * 4;
                    KVb[(e + 0) * TK + tl] = v.x;
                    KVb[(e + 1) * TK + tl] = v.y;
                    KVb[(e + 2) * TK + tl] = v.z;
                    KVb[(e + 3) * TK + tl] = v.w;
                }
            }
            __syncthreads();

            ull a00 = 0ull, a01 = 0ull, a10 = 0ull, a11 = 0ull;
#pragma unroll 8
            for (int e = 0; e < HS; ++e) {
                ull qq0 = QPb[e * QSTR + 2 * qp];
                ull qq1 = QPb[e * QSTR + 2 * qp + 1];
                ulonglong2 kk = *(const ulonglong2*)&KVb[e * TK + kq];
                a00 = ffma2(qq0, kk.x, a00);
                a01 = ffma2(qq0, kk.y, a01);
                a10 = ffma2(qq1, kk.x, a10);
                a11 = ffma2(qq1, kk.y, a11);
            }
            const int r0 = 2 * qp;
            float2 l0 = upk2(a00), h0 = upk2(a01), l1 = upk2(a10), h1 = upk2(a11);
            *(float4*)&SCb[r0 * SCP + t0 + kq] =
                make_float4(l0.x * 0.125f, l0.y * 0.125f, h0.x * 0.125f, h0.y * 0.125f);
            *(float4*)&SCb[(r0 + 1) * SCP + t0 + kq] =
                make_float4(l1.x * 0.125f, l1.y * 0.125f, h1.x * 0.125f, h1.y * 0.125f);
        }
        __syncthreads();  // all scores visible

        // --- softmax: warp w owns rows 2w, 2w+1 ---
#pragma unroll
        for (int rr = 0; rr < 2; ++rr) {
            const int r = 2 * w + rr;
            const int L = s0 + r + 1;
            float* scr = SCb + r * SCP;
            float m = -1e30f;
            for (int t = lane; t < L; t += 32) m = fmaxf(m, scr[t]);
#pragma unroll
            for (int o = 16; o; o >>= 1) m = fmaxf(m, __shfl_xor_sync(0xffffffffu, m, o));
            float sum = 0.f;
            for (int t = lane; t < L; t += 32) {
                float p = __expf(scr[t] - m);
                scr[t] = p;
                sum += p;
            }
#pragma unroll
            for (int o = 16; o; o >>= 1) sum += __shfl_xor_sync(0xffffffffu, sum, o);
            float invr = 1.f / sum;
            if (lane == 0) INVb[r] = invr;

            // accumulate head-mean partial into CTA-exclusive global region.
            // (overshoot into t>=L writes garbage that combine never reads)
            float4* gr = (float4*)(gAW + (size_t)r * SS);
            int nc4 = (L + 3) >> 2;
            if (hh == 0) {
                for (int c = lane; c < nc4; c += 32) {
                    float4 p = *(float4*)&scr[4 * c];
                    gr[c] = make_float4(p.x * invr, p.y * invr, p.z * invr, p.w * invr);
                }
            } else {
                for (int c = lane; c < nc4; c += 32) {
                    float4 g0 = gr[c];
                    float4 p = *(float4*)&scr[4 * c];
                    gr[c] = make_float4(g0.x + p.x * invr, g0.y + p.y * invr,
                                        g0.z + p.z * invr, g0.w + p.w * invr);
                }
            }
            // zero masked tail for PV
            for (int t = L + lane; t < tilemax; t += 32) scr[t] = 0.f;
        }
        __syncthreads();  // sc zeros + INV visible

        // --- PV ---
        ull p01 = 0ull, p23 = 0ull;
        for (int tile = 0; tile < ntiles; ++tile) {
            const int t0 = tile << 7;
            __syncthreads();
            {   // V tile: Vs[t][e], stride 68
                int tl = tid & 127, eh = tid >> 7;
                const float4* src = (const float4*)(Vb + (size_t)(t0 + tl) * HS) + eh * 8;
                float* dst = KVb + tl * 68 + eh * 32;
#pragma unroll
                for (int i = 0; i < 8; ++i) *(float4*)(dst + i * 4) = src[i];
            }
            __syncthreads();

            const float* scp = SCb + pv_qi * SCP + t0;
            const float* vbase = KVb + pv_e4 * 4;
#pragma unroll 8
            for (int t4 = 0; t4 < 32; ++t4) {
                float4 p4 = *(const float4*)(scp + 4 * t4);
                ulonglong2 v0 = *(const ulonglong2*)(vbase + (t4 * 4 + 0) * 68);
                ulonglong2 v1 = *(const ulonglong2*)(vbase + (t4 * 4 + 1) * 68);
                ulonglong2 v2 = *(const ulonglong2*)(vbase + (t4 * 4 + 2) * 68);
                ulonglong2 v3 = *(const ulonglong2*)(vbase + (t4 * 4 + 3) * 68);
                ull pp;
                pp = pk2(p4.x, p4.x); p01 = ffma2(pp, v0.x, p01); p23 = ffma2(pp, v0.y, p23);
                pp = pk2(p4.y, p4.y); p01 = ffma2(pp, v1.x, p01); p23 = ffma2(pp, v1.y, p23);
                pp = pk2(p4.z, p4.z); p01 = ffma2(pp, v2.x, p01); p23 = ffma2(pp, v2.y, p23);
                pp = pk2(p4.w, p4.w); p01 = ffma2(pp, v3.x, p01); p23 = ffma2(pp, v3.y, p23);
            }
        }
        {
            float ivq = INVb[pv_qi];
            ull iq = pk2(ivq, ivq);
            ctx01 = ffma2(p01, iq, ctx01);
            ctx23 = ffma2(p23, iq, ctx23);
        }
    }

    // write per-group partial context (sum over its 4 heads; /16 in oproj)
    float2 c01 = upk2(ctx01), c23 = upk2(ctx23);
    *(float4*)(g_O1p + (((size_t)(b * 4 + hg)) * SS + s0 + pv_qi) * HS + pv_e4 * 4) =
        make_float4(c01.x, c01.y, c23.x, c23.y);
}

// ---------------------------------------------------------------------------
// Combine: attn_out[b][s][t] = (sum_g AWp[g]) / 16, zero for t > s.
// ---------------------------------------------------------------------------
__global__ __launch_bounds__(256) void combine_kernel(float* __restrict__ attn_out) {
    const int s = blockIdx.x, b = blockIdx.y, c = threadIdx.x;
    float4* dst = (float4*)(attn_out + ((size_t)b * SS + s) * SS) + c;
    const int t0 = c * 4;
    if (t0 > s) { *dst = make_float4(0.f, 0.f, 0.f, 0.f); return; }
    float4 acc = make_float4(0.f, 0.f, 0.f, 0.f);
#pragma unroll
    for (int g = 0; g < 4; ++g) {
        const float4* p = (const float4*)(g_AWp + (((size_t)(b * 4 + g)) * SS + s) * SS) + c;
        float4 v = *p;
        acc.x += v.x; acc.y += v.y; acc.z += v.z; acc.w += v.w;
    }
    const float s16 = 1.f / 16.f;
    acc.x *= s16; acc.y *= s16; acc.z *= s16; acc.w *= s16;
    if (t0 + 1 > s) acc.y = 0.f;
    if (t0 + 2 > s) acc.z = 0.f;
    if (t0 + 3 > s) acc.w = 0.f;
    *dst = acc;
}

// ---------------------------------------------------------------------------
// Output projection, 16-row tiles: out[m,d] = (sum_g O1p[g][m,:])/16 @ Wo + bo
// ---------------------------------------------------------------------------
__global__ __launch_bounds__(256) void oproj2(const float* __restrict__ Wo,
                                              const float* __restrict__ bo,
                                              float* __restrict__ out) {
    __shared__ float O1s[TQ][HS];
    const int tid = threadIdx.x;
    const int m0 = blockIdx.x * TQ;
    const int b = m0 >> 10, s0 = m0 & 1023;
    {
        int row = tid >> 4, e4 = tid & 15;
        float4 acc = make_float4(0.f, 0.f, 0.f, 0.f);
#pragma unroll
        for (int g = 0; g < 4; ++g) {
            const float4* p = (const float4*)(g_O1p + (((size_t)(b * 4 + g)) * SS + s0 + row) * HS) + e4;
            float4 v = *p;
            acc.x += v.x; acc.y += v.y; acc.z += v.z; acc.w += v.w;
        }
        const float sc = 1.f / 16.f;
        *(float4*)&O1s[row][e4 * 4] = make_float4(acc.x * sc, acc.y * sc, acc.z * sc, acc.w * sc);
    }
    __syncthreads();

    float acc[4][16];
#pragma unroll
    for (int c = 0; c < 4; ++c)
#pragma unroll
        for (int r = 0; r < 16; ++r) acc[c][r] = 0.f;

    for (int e = 0; e < HS; ++e) {
        float o[16];
#pragma unroll
        for (int r = 0; r < 16; ++r) o[r] = O1s[r][e];
#pragma unroll
        for (int c = 0; c < 4; ++c) {
            float wv = Wo[(size_t)e * DD + c * 256 + tid];
#pragma unroll
            for (int r = 0; r < 16; ++r) acc[c][r] += o[r] * wv;
        }
    }
#pragma unroll
    for (int c = 0; c < 4; ++c) {
        int d = c * 256 + tid;
        float bd = bo[d];
#pragma unroll
        for (int r = 0; r < 16; ++r) out[(size_t)(m0 + r) * DD + d] = acc[c][r] + bd;
    }
}

// ---------------------------------------------------------------------------
// Launch
// ---------------------------------------------------------------------------
extern "C" void kernel_launch(void* const* d_in, const int* in_sizes, int n_in,
                              void* d_out, int out_size) {
    const float* queries = (const float*)d_in[0];
    const float* keys    = (const float*)d_in[1];
    const float* values  = (const float*)d_in[2];
    const float* Wq = (const float*)d_in[4];
    const float* bq = (const float*)d_in[5];
    const float* Wk = (const float*)d_in[6];
    const float* bk = (const float*)d_in[7];
    const float* Wv = (const float*)d_in[8];
    const float* bv = (const float*)d_in[9];
    const float* Wo = (const float*)d_in[10];
    const float* bo = (const float*)d_in[11];

    float* out_main = (float*)d_out;                         // [B,S,D]
    float* out_attn = (float*)d_out + (size_t)BB * SS * DD;  // [B,S,S]

    float* dQ; cudaGetSymbolAddress((void**)&dQ, g_Q);
    float* dK; cudaGetSymbolAddress((void**)&dK, g_K);
    float* dV; cudaGetSymbolAddress((void**)&dV, g_V);

    static int attr_set = 0;
    if (!attr_set) {
        cudaFuncSetAttribute(attn3_kernel, cudaFuncAttributeMaxDynamicSharedMemorySize,
                             ATTN_SMEM);
        attr_set = 1;
    }

    proj_gemm<<<dim3(HH, (BB * SS) / 64), 256>>>(queries, Wq, bq, dQ,
                                                 HH * SS * HS, SS * HS);
    proj_gemm<<<dim3(HH, (BB * SS) / 64), 256>>>(keys, Wk, bk, dK,
                                                 HH * SS * HS, SS * HS);
    proj_gemm<<<dim3(1, (BB * SS) / 64), 256>>>(values, Wv, bv, dV,
                                                SS * HS, 0);

    attn3_kernel<<<dim3(SS / TQ, 4, BB), 256, ATTN_SMEM>>>();

    combine_kernel<<<dim3(SS, BB), 256>>>(out_attn);
    oproj2<<<(BB * SS) / TQ, 256>>>(Wo, bo, out_main);

    (void)in_sizes; (void)n_in; (void)out_size;
}

// round 15
// speedup vs baseline: 1.0041x; 1.0041x over previous
#include <cuda_runtime.h>

#define BB 4
#define SS 1024
#define DD 1024
#define HH 16
#define HS 64
#define TQ 16
#define TK 128
#define SCP 1028
#define QSTR 17

typedef unsigned long long ull;

// Scratch (no allocations allowed -> __device__ globals)
__device__ float g_Q[BB * HH * SS * HS];     // [b,h,s,e] 16 MB
__device__ float g_K[BB * HH * SS * HS];     // [b,h,s,e] 16 MB
__device__ float g_V[BB * SS * HS];          // [b,s,e]    1 MB
__device__ float g_AWp[BB * 4 * SS * SS];    // per-headgroup partial attn  67 MB
__device__ float g_O1p[BB * 4 * SS * HS];    // per-headgroup partial ctx    4 MB

// ---- packed fp32x2 helpers (bit-exact fp32 FMA, 2x throughput) ----
__device__ __forceinline__ ull pk2(float x, float y) {
    ull r; asm("mov.b64 %0,{%1,%2};" : "=l"(r) : "f"(x), "f"(y)); return r;
}
__device__ __forceinline__ float2 upk2(ull v) {
    float2 r; asm("mov.b64 {%0,%1},%2;" : "=f"(r.x), "=f"(r.y) : "l"(v)); return r;
}
__device__ __forceinline__ ull ffma2(ull a, ull b, ull c) {
    ull d; asm("fma.rn.f32x2 %0,%1,%2,%3;" : "=l"(d) : "l"(a), "l"(b), "l"(c)); return d;
}

// ---------------------------------------------------------------------------
// Projection GEMM with FFMA2: out(m,n) = A[m,:] @ W[h][:,n] + bias
// Tile 64x64, 256 threads, 4x4 micro-tile (as 4x2 packed pairs), K-tile 16.
// ---------------------------------------------------------------------------
__global__ void proj_gemm(const float* __restrict__ A, const float* __restrict__ W,
                          const float* __restrict__ bias, float* __restrict__ out,
                          int strideB, int strideH) {
    __shared__ float As[16][68];   // 68: keeps float4 reads 16B-aligned
    __shared__ float Bs[16][64];
    const int tid = threadIdx.x;
    const int tx = tid & 15, ty = tid >> 4;
    const int n0 = blockIdx.x * 64;
    const int m0 = blockIdx.y * 64;
    const float* Wh = W + (size_t)blockIdx.x * (DD * HS);

    ull acc[4][2];
#pragma unroll
    for (int i = 0; i < 4; ++i) { acc[i][0] = 0ull; acc[i][1] = 0ull; }

    for (int k0 = 0; k0 < DD; k0 += 16) {
        {
            int ml = tid >> 2, kk4 = (tid & 3) * 4;
            float4 a4 = *(const float4*)(A + (size_t)(m0 + ml) * DD + k0 + kk4);
            As[kk4 + 0][ml] = a4.x;
            As[kk4 + 1][ml] = a4.y;
            As[kk4 + 2][ml] = a4.z;
            As[kk4 + 3][ml] = a4.w;
        }
        {
            int kk = tid >> 4, nl4 = (tid & 15) * 4;
            *(float4*)&Bs[kk][nl4] = *(const float4*)(Wh + (size_t)(k0 + kk) * HS + nl4);
        }
        __syncthreads();

#pragma unroll
        for (int kk = 0; kk < 16; ++kk) {
            float4 a4 = *(const float4*)&As[kk][ty * 4];
            ulonglong2 bb = *(const ulonglong2*)&Bs[kk][tx * 4];
            ull aa;
            aa = pk2(a4.x, a4.x); acc[0][0] = ffma2(aa, bb.x, acc[0][0]); acc[0][1] = ffma2(aa, bb.y, acc[0][1]);
            aa = pk2(a4.y, a4.y); acc[1][0] = ffma2(aa, bb.x, acc[1][0]); acc[1][1] = ffma2(aa, bb.y, acc[1][1]);
            aa = pk2(a4.z, a4.z); acc[2][0] = ffma2(aa, bb.x, acc[2][0]); acc[2][1] = ffma2(aa, bb.y, acc[2][1]);
            aa = pk2(a4.w, a4.w); acc[3][0] = ffma2(aa, bb.x, acc[3][0]); acc[3][1] = ffma2(aa, bb.y, acc[3][1]);
        }
        __syncthreads();
    }

#pragma unroll
    for (int i = 0; i < 4; ++i) {
        int m = m0 + ty * 4 + i;
        int b = m >> 10, srow = m & 1023;
        float* orow = out + (size_t)b * strideB + (size_t)blockIdx.x * strideH + (size_t)srow * HS;
        float2 lo = upk2(acc[i][0]), hi = upk2(acc[i][1]);
        int nl = tx * 4;
        orow[nl + 0] = lo.x + bias[n0 + nl + 0];
        orow[nl + 1] = lo.y + bias[n0 + nl + 1];
        orow[nl + 2] = hi.x + bias[n0 + nl + 2];
        orow[nl + 3] = hi.y + bias[n0 + nl + 3];
    }
}

// ---------------------------------------------------------------------------
// Attention v3: one CTA per (b, qtile=16 rows, headgroup of 4 heads).
// 256 threads, ~109KB smem -> 2 CTAs/SM. FFMA2 inner loops. Partial head-mean
// attn rows accumulate into a CTA-exclusive global buffer (no atomics).
// ---------------------------------------------------------------------------
// smem float offsets:
//   SC : 16*1028            @ 0       (scores row buffer)
//   KV : 8704               @ 16448   (KsT: 64 x 128 | Vs: 128 x 68, union)
//   QP : 64*17 ull (=2176f) @ 25152   (Q splat-pairs, [e][qi])
//   INV: 16                 @ 27328
#define KV_OFF   16448
#define QP_OFF   25152
#define INV_OFF  27328
#define ATTN_SMEM ((INV_OFF + 16) * 4)   // 109376 bytes

__global__ __launch_bounds__(256, 2) void attn3_kernel() {
    extern __shared__ float sm[];
    float* SCb = sm;
    float* KVb = sm + KV_OFF;
    ull*   QPb = (ull*)(sm + QP_OFF);
    float* INVb = sm + INV_OFF;

    const int qt = 63 - (int)blockIdx.x;   // reversed for load balance
    const int hg = blockIdx.y;
    const int b  = blockIdx.z;
    const int tid = threadIdx.x;
    const int lane = tid & 31;
    const int w = tid >> 5;

    const int s0 = qt * TQ;
    const int ntiles = (s0 + TQ + TK - 1) >> 7;
    const int tilemax = ntiles << 7;

    // scores mapping: warp w owns t-window [16w,16w+16) of each tile, all 16 q.
    // thread: q-pair = lane>>2, t-quad = lane&3.
    const int qp = lane >> 2;                  // 0..7 -> rows 2qp, 2qp+1
    const int kq = 16 * w + 4 * (lane & 3);    // t offset within tile

    // PV mapping: warp tile 8q x 16e, thread 1q x 4e
    const int pv_qi = (w >> 2) * 8 + (lane >> 2);
    const int pv_e4 = (w & 3) * 4 + (lane & 3);

    float* gAW = g_AWp + (((size_t)(b * 4 + hg)) * SS + s0) * SS;
    const float* Vb = g_V + (size_t)b * SS * HS;

    ull ctx01 = 0ull, ctx23 = 0ull;

    for (int hh = 0; hh < 4; ++hh) {
        const int h = hg * 4 + hh;
        const size_t bh = (size_t)(b * HH + h);
        __syncthreads();  // prev head's PV/INV readers done

        // --- load Q tile as splat pairs: QP[e][qi] = (q,q) ---
        {
            int qi = tid & 15, eB = tid >> 4;
            float4 v = *(const float4*)(g_Q + (bh * SS + s0 + qi) * HS + eB * 4);
            QPb[(eB * 4 + 0) * QSTR + qi] = pk2(v.x, v.x);
            QPb[(eB * 4 + 1) * QSTR + qi] = pk2(v.y, v.y);
            QPb[(eB * 4 + 2) * QSTR + qi] = pk2(v.z, v.z);
            QPb[(eB * 4 + 3) * QSTR + qi] = pk2(v.w, v.w);
        }

        // --- scores ---
        for (int tile = 0; tile < ntiles; ++tile) {
            const int t0 = tile << 7;
            __syncthreads();
            {   // K tile transposed: KsT[e][t]
                int tl = tid & 127, eh = tid >> 7;
                const float4* src = (const float4*)(g_K + (bh * SS + t0 + tl) * HS) + eh * 8;
#pragma unroll
                for (int i = 0; i < 8; ++i) {
                    float4 v = src[i];
                    int e = eh * 32 + i * 4;
                    KVb[(e + 0) * TK + tl] = v.x;
                    KVb[(e + 1) * TK + tl] = v.y;
                    KVb[(e + 2) * TK + tl] = v.z;
                    KVb[(e + 3) * TK + tl] = v.w;
                }
            }
            __syncthreads();

            ull a00 = 0ull, a01 = 0ull, a10 = 0ull, a11 = 0ull;
#pragma unroll 8
            for (int e = 0; e < HS; ++e) {
                ull qq0 = QPb[e * QSTR + 2 * qp];
                ull qq1 = QPb[e * QSTR + 2 * qp + 1];
                ulonglong2 kk = *(const ulonglong2*)&KVb[e * TK + kq];
                a00 = ffma2(qq0, kk.x, a00);
                a01 = ffma2(qq0, kk.y, a01);
                a10 = ffma2(qq1, kk.x, a10);
                a11 = ffma2(qq1, kk.y, a11);
            }
            const int r0 = 2 * qp;
            float2 l0 = upk2(a00), h0 = upk2(a01), l1 = upk2(a10), h1 = upk2(a11);
            *(float4*)&SCb[r0 * SCP + t0 + kq] =
                make_float4(l0.x * 0.125f, l0.y * 0.125f, h0.x * 0.125f, h0.y * 0.125f);
            *(float4*)&SCb[(r0 + 1) * SCP + t0 + kq] =
                make_float4(l1.x * 0.125f, l1.y * 0.125f, h1.x * 0.125f, h1.y * 0.125f);
        }
        __syncthreads();  // all scores visible

        // --- softmax: warp w owns rows 2w, 2w+1 ---
#pragma unroll
        for (int rr = 0; rr < 2; ++rr) {
            const int r = 2 * w + rr;
            const int L = s0 + r + 1;
            float* scr = SCb + r * SCP;
            float m = -1e30f;
            for (int t = lane; t < L; t += 32) m = fmaxf(m, scr[t]);
#pragma unroll
            for (int o = 16; o; o >>= 1) m = fmaxf(m, __shfl_xor_sync(0xffffffffu, m, o));
            float sum = 0.f;
            for (int t = lane; t < L; t += 32) {
                float p = __expf(scr[t] - m);
                scr[t] = p;
                sum += p;
            }
#pragma unroll
            for (int o = 16; o; o >>= 1) sum += __shfl_xor_sync(0xffffffffu, sum, o);
            float invr = 1.f / sum;
            if (lane == 0) INVb[r] = invr;

            // accumulate head-mean partial into CTA-exclusive global region.
            // (overshoot into t>=L writes garbage that combine never reads)
            float4* gr = (float4*)(gAW + (size_t)r * SS);
            int nc4 = (L + 3) >> 2;
            if (hh == 0) {
                for (int c = lane; c < nc4; c += 32) {
                    float4 p = *(float4*)&scr[4 * c];
                    gr[c] = make_float4(p.x * invr, p.y * invr, p.z * invr, p.w * invr);
                }
            } else {
                for (int c = lane; c < nc4; c += 32) {
                    float4 g0 = gr[c];
                    float4 p = *(float4*)&scr[4 * c];
                    gr[c] = make_float4(g0.x + p.x * invr, g0.y + p.y * invr,
                                        g0.z + p.z * invr, g0.w + p.w * invr);
                }
            }
            // zero masked tail for PV
            for (int t = L + lane; t < tilemax; t += 32) scr[t] = 0.f;
        }
        __syncthreads();  // sc zeros + INV visible

        // --- PV ---
        ull p01 = 0ull, p23 = 0ull;
        for (int tile = 0; tile < ntiles; ++tile) {
            const int t0 = tile << 7;
            __syncthreads();
            {   // V tile: Vs[t][e], stride 68
                int tl = tid & 127, eh = tid >> 7;
                const float4* src = (const float4*)(Vb + (size_t)(t0 + tl) * HS) + eh * 8;
                float* dst = KVb + tl * 68 + eh * 32;
#pragma unroll
                for (int i = 0; i < 8; ++i) *(float4*)(dst + i * 4) = src[i];
            }
            __syncthreads();

            const float* scp = SCb + pv_qi * SCP + t0;
            const float* vbase = KVb + pv_e4 * 4;
#pragma unroll 8
            for (int t4 = 0; t4 < 32; ++t4) {
                float4 p4 = *(const float4*)(scp + 4 * t4);
                ulonglong2 v0 = *(const ulonglong2*)(vbase + (t4 * 4 + 0) * 68);
                ulonglong2 v1 = *(const ulonglong2*)(vbase + (t4 * 4 + 1) * 68);
                ulonglong2 v2 = *(const ulonglong2*)(vbase + (t4 * 4 + 2) * 68);
                ulonglong2 v3 = *(const ulonglong2*)(vbase + (t4 * 4 + 3) * 68);
                ull pp;
                pp = pk2(p4.x, p4.x); p01 = ffma2(pp, v0.x, p01); p23 = ffma2(pp, v0.y, p23);
                pp = pk2(p4.y, p4.y); p01 = ffma2(pp, v1.x, p01); p23 = ffma2(pp, v1.y, p23);
                pp = pk2(p4.z, p4.z); p01 = ffma2(pp, v2.x, p01); p23 = ffma2(pp, v2.y, p23);
                pp = pk2(p4.w, p4.w); p01 = ffma2(pp, v3.x, p01); p23 = ffma2(pp, v3.y, p23);
            }
        }
        {
            float ivq = INVb[pv_qi];
            ull iq = pk2(ivq, ivq);
            ctx01 = ffma2(p01, iq, ctx01);
            ctx23 = ffma2(p23, iq, ctx23);
        }
    }

    // write per-group partial context (sum over its 4 heads; /16 in oproj)
    float2 c01 = upk2(ctx01), c23 = upk2(ctx23);
    *(float4*)(g_O1p + (((size_t)(b * 4 + hg)) * SS + s0 + pv_qi) * HS + pv_e4 * 4) =
        make_float4(c01.x, c01.y, c23.x, c23.y);
}

// ---------------------------------------------------------------------------
// Combine: attn_out[b][s][t] = (sum_g AWp[g]) / 16, zero for t > s.
// ---------------------------------------------------------------------------
__global__ __launch_bounds__(256) void combine_kernel(float* __restrict__ attn_out) {
    const int s = blockIdx.x, b = blockIdx.y, c = threadIdx.x;
    float4* dst = (float4*)(attn_out + ((size_t)b * SS + s) * SS) + c;
    const int t0 = c * 4;
    if (t0 > s) { *dst = make_float4(0.f, 0.f, 0.f, 0.f); return; }
    float4 acc = make_float4(0.f, 0.f, 0.f, 0.f);
#pragma unroll
    for (int g = 0; g < 4; ++g) {
        const float4* p = (const float4*)(g_AWp + (((size_t)(b * 4 + g)) * SS + s) * SS) + c;
        float4 v = *p;
        acc.x += v.x; acc.y += v.y; acc.z += v.z; acc.w += v.w;
    }
    const float s16 = 1.f / 16.f;
    acc.x *= s16; acc.y *= s16; acc.z *= s16; acc.w *= s16;
    if (t0 + 1 > s) acc.y = 0.f;
    if (t0 + 2 > s) acc.z = 0.f;
    if (t0 + 3 > s) acc.w = 0.f;
    *dst = acc;
}

// ---------------------------------------------------------------------------
// Output projection, 16-row tiles: out[m,d] = (sum_g O1p[g][m,:])/16 @ Wo + bo
// ---------------------------------------------------------------------------
__global__ __launch_bounds__(256) void oproj2(const float* __restrict__ Wo,
                                              const float* __restrict__ bo,
                                              float* __restrict__ out) {
    __shared__ float O1s[TQ][HS];
    const int tid = threadIdx.x;
    const int m0 = blockIdx.x * TQ;
    const int b = m0 >> 10, s0 = m0 & 1023;
    {
        int row = tid >> 4, e4 = tid & 15;
        float4 acc = make_float4(0.f, 0.f, 0.f, 0.f);
#pragma unroll
        for (int g = 0; g < 4; ++g) {
            const float4* p = (const float4*)(g_O1p + (((size_t)(b * 4 + g)) * SS + s0 + row) * HS) + e4;
            float4 v = *p;
            acc.x += v.x; acc.y += v.y; acc.z += v.z; acc.w += v.w;
        }
        const float sc = 1.f / 16.f;
        *(float4*)&O1s[row][e4 * 4] = make_float4(acc.x * sc, acc.y * sc, acc.z * sc, acc.w * sc);
    }
    __syncthreads();

    float acc[4][16];
#pragma unroll
    for (int c = 0; c < 4; ++c)
#pragma unroll
        for (int r = 0; r < 16; ++r) acc[c][r] = 0.f;

    for (int e = 0; e < HS; ++e) {
        float o[16];
#pragma unroll
        for (int r = 0; r < 16; ++r) o[r] = O1s[r][e];
#pragma unroll
        for (int c = 0; c < 4; ++c) {
            float wv = Wo[(size_t)e * DD + c * 256 + tid];
#pragma unroll
            for (int r = 0; r < 16; ++r) acc[c][r] += o[r] * wv;
        }
    }
#pragma unroll
    for (int c = 0; c < 4; ++c) {
        int d = c * 256 + tid;
        float bd = bo[d];
#pragma unroll
        for (int r = 0; r < 16; ++r) out[(size_t)(m0 + r) * DD + d] = acc[c][r] + bd;
    }
}

// ---------------------------------------------------------------------------
// Launch
// ---------------------------------------------------------------------------
extern "C" void kernel_launch(void* const* d_in, const int* in_sizes, int n_in,
                              void* d_out, int out_size) {
    const float* queries = (const float*)d_in[0];
    const float* keys    = (const float*)d_in[1];
    const float* values  = (const float*)d_in[2];
    const float* Wq = (const float*)d_in[4];
    const float* bq = (const float*)d_in[5];
    const float* Wk = (const float*)d_in[6];
    const float* bk = (const float*)d_in[7];
    const float* Wv = (const float*)d_in[8];
    const float* bv = (const float*)d_in[9];
    const float* Wo = (const float*)d_in[10];
    const float* bo = (const float*)d_in[11];

    float* out_main = (float*)d_out;                         // [B,S,D]
    float* out_attn = (float*)d_out + (size_t)BB * SS * DD;  // [B,S,S]

    float* dQ; cudaGetSymbolAddress((void**)&dQ, g_Q);
    float* dK; cudaGetSymbolAddress((void**)&dK, g_K);
    float* dV; cudaGetSymbolAddress((void**)&dV, g_V);

    static int attr_set = 0;
    if (!attr_set) {
        cudaFuncSetAttribute(attn3_kernel, cudaFuncAttributeMaxDynamicSharedMemorySize,
                             ATTN_SMEM);
        attr_set = 1;
    }

    proj_gemm<<<dim3(HH, (BB * SS) / 64), 256>>>(queries, Wq, bq, dQ,
                                                 HH * SS * HS, SS * HS);
    proj_gemm<<<dim3(HH, (BB * SS) / 64), 256>>>(keys, Wk, bk, dK,
                                                 HH * SS * HS, SS * HS);
    proj_gemm<<<dim3(1, (BB * SS) / 64), 256>>>(values, Wv, bv, dV,
                                                SS * HS, 0);

    attn3_kernel<<<dim3(SS / TQ, 4, BB), 256, ATTN_SMEM>>>();

    combine_kernel<<<dim3(SS, BB), 256>>>(out_attn);
    oproj2<<<(BB * SS) / TQ, 256>>>(Wo, bo, out_main);

    (void)in_sizes; (void)n_in; (void)out_size;
}